// round 10
// baseline (speedup 1.0000x reference)
#include <cuda_runtime.h>
#include <cstdint>

#define B_  8
#define H_  224
#define W_  224
#define C_  192
#define QT  8        // q positions per block
#define NQ  2        // q per thread
#define PAIRS 32     // channel pairs (threadIdx.x)
#define QTH  4       // q-thread groups (threadIdx.y)
#define NTHREADS 128
#define RH  28       // output rows per block (28 % 7 == 0)
#define SROW 14      // staged columns per row (QT + 6)
#define STAGES 8
#define STAGE_BYTES (SROW * 64 * 4)          // 3584 B per stage
#define RING_BYTES  (STAGES * STAGE_BYTES)   // 28672 B
#define ROWSZ (W_ * C_)
#define IMGSZ (H_ * W_ * C_)

typedef unsigned long long u64;

__device__ __forceinline__ void fma2(u64 &d, u64 a, u64 b) {
    asm("fma.rn.f32x2 %0, %1, %2, %0;" : "+l"(d) : "l"(a), "l"(b));
}
__device__ __forceinline__ u64 pack2(float lo, float hi) {
    return (u64)__float_as_uint(lo) | ((u64)__float_as_uint(hi) << 32);
}
__device__ __forceinline__ void cpasync16(uint32_t dst, const float* src) {
    asm volatile("cp.async.cg.shared.global [%0], [%1], 16;" :: "r"(dst), "l"(src));
}
__device__ __forceinline__ void cp_commit() {
    asm volatile("cp.async.commit_group;" ::: "memory");
}
__device__ __forceinline__ void cp_wait2() {
    asm volatile("cp.async.wait_group 2;" ::: "memory");
}
__device__ __forceinline__ void cp_wait0() {
    asm volatile("cp.async.wait_group 0;" ::: "memory");
}
__device__ __forceinline__ uint32_t smem_u32(const void* p) {
    uint32_t a;
    asm("{ .reg .u64 t; cvta.to.shared.u64 t, %1; cvt.u32.u64 %0, t; }" : "=r"(a) : "l"(p));
    return a;
}

// Compute half-step at row phase T7 (t % 7), stage byte offset SOFF.
// Kernel rows i in [ILO, IHI] only (wedge pruning: warm-up t<6 skips i<6-t,
// tail t>RH-1 skips i>RH+5-t). Slot (T7+2)%7 completes this step.
#define STEP_RANGE(T7, ILO, IHI, SOFF, DOSTORE) do {                          \
    const char* sb = (const char*)sbuf + (SOFF) + ty * (NQ * 256) + tx * 8;   \
    u64 w[8];                                                                 \
    _Pragma("unroll")                                                         \
    for (int d = 0; d < 8; ++d)                                               \
        w[d] = *(const u64*)(sb + d * 256);                                   \
    _Pragma("unroll")                                                         \
    for (int i = 0; i < 7; ++i) {                                             \
        if (i >= (ILO) && i <= (IHI)) {                                       \
            const int s = ((T7) + i + 2) % 7;                                 \
            _Pragma("unroll")                                                 \
            for (int j = 0; j < 7; ++j) {                                     \
                const u64 kv = kreg[i * 7 + j];                               \
                fma2(acc[s][0], kv, w[6 - j]);                                \
                fma2(acc[s][1], kv, w[7 - j]);                                \
            }                                                                 \
        }                                                                     \
    }                                                                         \
    {                                                                         \
        const int so = ((T7) + 2) % 7;                                        \
        if (DOSTORE) {                                                        \
            *(u64*)(out + outOff)      = acc[so][0];                          \
            *(u64*)(out + outOff + C_) = acc[so][1];                          \
            outOff += ROWSZ;                                                  \
        }                                                                     \
        acc[so][0] = 0ULL; acc[so][1] = 0ULL;                                 \
    }                                                                         \
} while (0)

// Macro step: one wait + one barrier + one commit group for TWO rows.
#define MACRO2R(T7a, LOa, T7b, LOb, DOSTORE) do {                             \
    cp_wait2();                                                               \
    __syncthreads();                                                          \
    {                                                                         \
        const uint32_t dA = sdst + offP;                                      \
        cpasync16(dA, rowPtr + colOff0);                                      \
        if (has1) cpasync16(dA + 2048, rowPtr + colOff1);                     \
        rowPtr += ROWSZ; if (rowPtr >= xEnd) rowPtr -= IMGSZ;                 \
        uint32_t p2 = offP + STAGE_BYTES;                                     \
        if (p2 >= RING_BYTES) p2 -= RING_BYTES;                               \
        const uint32_t dB = sdst + p2;                                        \
        cpasync16(dB, rowPtr + colOff0);                                      \
        if (has1) cpasync16(dB + 2048, rowPtr + colOff1);                     \
        rowPtr += ROWSZ; if (rowPtr >= xEnd) rowPtr -= IMGSZ;                 \
        cp_commit();                                                          \
        offP += 2 * STAGE_BYTES; if (offP >= RING_BYTES) offP -= RING_BYTES;  \
    }                                                                         \
    STEP_RANGE(T7a, LOa, 6, offCa, DOSTORE);                                  \
    offCa += 2 * STAGE_BYTES; if (offCa >= RING_BYTES) offCa -= RING_BYTES;   \
    STEP_RANGE(T7b, LOb, 6, offCb, DOSTORE);                                  \
    offCb += 2 * STAGE_BYTES; if (offCb >= RING_BYTES) offCb -= RING_BYTES;   \
} while (0)

// 7 macro steps = 14 rows (acc phase period). Starts at t%7 == 6.
#define GROUP7M()                                                             \
    MACRO2R(6, 0, 0, 0, 1); MACRO2R(1, 0, 2, 0, 1); MACRO2R(3, 0, 4, 0, 1);   \
    MACRO2R(5, 0, 6, 0, 1); MACRO2R(0, 0, 1, 0, 1); MACRO2R(2, 0, 3, 0, 1);   \
    MACRO2R(4, 0, 5, 0, 1)

#define TAILSTEP(T7, IHI, CUR) do {                                           \
    STEP_RANGE(T7, 0, IHI, CUR, 1);                                           \
    CUR += 2 * STAGE_BYTES; if (CUR >= RING_BYTES) CUR -= RING_BYTES;         \
} while (0)

__global__ void __launch_bounds__(NTHREADS, 3)
dwconv_pipe5(const float* __restrict__ x, const float* __restrict__ kern,
             float* __restrict__ out)
{
    __shared__ float sbuf[STAGES][SROW][64];   // 28,672 B (8-stage ring)

    const int tx  = threadIdx.x;           // channel pair 0..31
    const int ty  = threadIdx.y;           // q group 0..3
    const int tid = ty * PAIRS + tx;

    const int wt = blockIdx.x;              // 0..27
    const int ht = blockIdx.y;              // 0..7
    const int bz = blockIdx.z;              // 0..23
    const int b  = bz / 3;
    const int g  = bz % 3;

    const int qbase = wt * QT;
    const int p0    = ht * RH;              // p0 % 7 == 0
    const int cbase = g * 64;
    const int c0    = cbase + 2 * tx;

    // ---- 49 kernel taps for this channel pair -> registers (f32x2) ----
    u64 kreg[49];
    #pragma unroll
    for (int t = 0; t < 49; ++t)
        kreg[t] = pack2(kern[c0 * 49 + t], kern[(c0 + 1) * 49 + t]);

    // ---- cp.async staging plan: 224 float4 per stage, threads 0..95 take 2 ----
    const int s0 = tid >> 4, v0 = tid & 15;             // cols 0..7
    const bool has1 = tid < 96;
    const int s1 = (tid + 128) >> 4;                    // cols 8..13
    int qg0 = qbase - 3 + s0; qg0 += (qg0 < 0) ? W_ : 0; qg0 -= (qg0 >= W_) ? W_ : 0;
    int qg1 = qbase - 3 + s1; qg1 += (qg1 < 0) ? W_ : 0; qg1 -= (qg1 >= W_) ? W_ : 0;
    const int colOff0 = qg0 * C_ + cbase + v0 * 4;
    const int colOff1 = qg1 * C_ + cbase + v0 * 4;
    const uint32_t sdst = smem_u32(&sbuf[0][0][0]) + (uint32_t)(s0 * 256 + v0 * 16);

    // row cursor (circular over H, pointer-only)
    const float* const xBase = x + b * IMGSZ;
    const float* const xEnd  = xBase + IMGSZ;
    const float* rowPtr = xBase + (p0 - 3 < 0 ? p0 - 3 + H_ : p0 - 3) * ROWSZ;

    // ---- prologue: stage rows 0..5 into stages 0..5 (3 groups of 2 rows) ----
    #pragma unroll
    for (int pr = 0; pr < 3; ++pr) {
        uint32_t dA = sdst + (2 * pr) * STAGE_BYTES;
        cpasync16(dA, rowPtr + colOff0);
        if (has1) cpasync16(dA + 2048, rowPtr + colOff1);
        rowPtr += ROWSZ; if (rowPtr >= xEnd) rowPtr -= IMGSZ;
        uint32_t dB = sdst + (2 * pr + 1) * STAGE_BYTES;
        cpasync16(dB, rowPtr + colOff0);
        if (has1) cpasync16(dB + 2048, rowPtr + colOff1);
        rowPtr += ROWSZ; if (rowPtr >= xEnd) rowPtr -= IMGSZ;
        cp_commit();
    }

    uint32_t offCa = 0;
    uint32_t offCb = STAGE_BYTES;
    uint32_t offP  = 6 * STAGE_BYTES;

    // 7 rolling accumulators (static slots), f32x2 x NQ
    u64 acc[7][2];
    #pragma unroll
    for (int m = 0; m < 7; ++m) { acc[m][0] = 0ULL; acc[m][1] = 0ULL; }

    const int qOut = qbase + ty * NQ;
    int outOff = ((b * H_ + p0) * W_ + qOut) * C_ + c0;

    // ---- warm-up: rows t = 0..5, wedge-pruned (i >= 6-t), no stores ----
    MACRO2R(0, 6, 1, 5, 0);
    MACRO2R(2, 4, 3, 3, 0);
    MACRO2R(4, 2, 5, 1, 0);

    // ---- main: rows t = 6..19, one 7-macro group ----
    GROUP7M();
    // ---- main remainder: rows t = 20..27 ----
    MACRO2R(6, 0, 0, 0, 1);
    MACRO2R(1, 0, 2, 0, 1);
    MACRO2R(3, 0, 4, 0, 1);
    MACRO2R(5, 0, 6, 0, 1);

    // ---- tail: rows t = 28..33, wedge-pruned (i <= 33-t), all data staged ----
    cp_wait0();
    __syncthreads();
    TAILSTEP(0, 5, offCa);
    TAILSTEP(1, 4, offCb);
    TAILSTEP(2, 3, offCa);
    TAILSTEP(3, 2, offCb);
    TAILSTEP(4, 1, offCa);
    TAILSTEP(5, 0, offCb);
}

extern "C" void kernel_launch(void* const* d_in, const int* in_sizes, int n_in,
                              void* d_out, int out_size) {
    const float* x    = (const float*)d_in[0];   // (8,224,224,192) fp32
    const float* kern = (const float*)d_in[1];   // (192,7,7) fp32
    float* out        = (float*)d_out;           // (8,224,224,192) fp32

    dim3 grid(W_ / QT, H_ / RH, B_ * 3);  // 28 x 8 x 24 = 5376 blocks
    dim3 block(PAIRS, QTH, 1);            // 128 threads
    dwconv_pipe5<<<grid, block>>>(x, kern, out);
}

// round 11
// speedup vs baseline: 1.0525x; 1.0525x over previous
#include <cuda_runtime.h>
#include <cstdint>

#define B_  8
#define H_  224
#define W_  224
#define C_  192
#define QT  8        // q positions per block
#define NQ  2        // q per thread
#define PAIRS 32     // channel pairs (threadIdx.x)
#define QTH  4       // q-thread groups (threadIdx.y)
#define NTHREADS 128
#define RH  56       // output rows per block
#define SROW 14      // staged columns per row (QT + 6)
#define STAGES 12
#define STAGE_BYTES 3584                      // 14 cols * 64 ch * 4 B
#define GROUP_BYTES (4 * STAGE_BYTES)         // 14336 B (4-row group)
#define RING_BYTES  (STAGES * STAGE_BYTES)    // 43008 B
#define ROWSZ (W_ * C_)
#define IMGSZ (H_ * W_ * C_)

typedef unsigned long long u64;

__device__ __forceinline__ void fma2(u64 &d, u64 a, u64 b) {
    asm("fma.rn.f32x2 %0, %1, %2, %0;" : "+l"(d) : "l"(a), "l"(b));
}
__device__ __forceinline__ u64 pack2(float lo, float hi) {
    return (u64)__float_as_uint(lo) | ((u64)__float_as_uint(hi) << 32);
}
__device__ __forceinline__ void cpasync16(uint32_t dst, const float* src) {
    asm volatile("cp.async.cg.shared.global [%0], [%1], 16;" :: "r"(dst), "l"(src));
}
__device__ __forceinline__ void cp_commit() {
    asm volatile("cp.async.commit_group;" ::: "memory");
}
__device__ __forceinline__ void cp_wait1() {
    asm volatile("cp.async.wait_group 1;" ::: "memory");
}
__device__ __forceinline__ void cp_wait0() {
    asm volatile("cp.async.wait_group 0;" ::: "memory");
}
__device__ __forceinline__ uint32_t smem_u32(const void* p) {
    uint32_t a;
    asm("{ .reg .u64 t; cvta.to.shared.u64 t, %1; cvt.u32.u64 %0, t; }" : "=r"(a) : "l"(p));
    return a;
}

// Stage 4 rows (rowPtr..rowPtr+3, circular) into the group at ring offset offP.
// Linear-blob mapping: byte = offP + 16*(tid + 128k)  ==  consumer layout
// r*3584 + s*256 + v*16 (since idx = r*224 + s*16 + v). 7 cp.async per thread,
// perfectly balanced across all warps. Advances rowPtr (+4 rows) and offP.
#define STAGE_GROUP() do {                                                    \
    const float* rb1 = rowPtr + ROWSZ;     if (rb1 >= xEnd) rb1 -= IMGSZ;     \
    const float* rb2 = rowPtr + 2 * ROWSZ; if (rb2 >= xEnd) rb2 -= IMGSZ;     \
    const float* rb3 = rowPtr + 3 * ROWSZ; if (rb3 >= xEnd) rb3 -= IMGSZ;     \
    const uint32_t sp = sdst + offP;                                          \
    cpasync16(sp,         rowPtr + colOff0);                                  \
    cpasync16(sp + 2048,  (cls1 ? rowPtr : rb1) + colOff1);                   \
    cpasync16(sp + 4096,  rb1 + colOff2);                                     \
    cpasync16(sp + 6144,  (cls3 ? rb1 : rb2) + colOff3);                      \
    cpasync16(sp + 8192,  rb2 + colOff4);                                     \
    cpasync16(sp + 10240, (cls5 ? rb2 : rb3) + colOff5);                      \
    cpasync16(sp + 12288, rb3 + colOff6);                                     \
    cp_commit();                                                              \
    rowPtr += 4 * ROWSZ; if (rowPtr >= xEnd) rowPtr -= IMGSZ;                 \
    offP += GROUP_BYTES; if (offP >= RING_BYTES) offP -= RING_BYTES;          \
} while (0)

// Compute one row-step at phase T7 (t % 7), consuming the stage at offC.
// Kernel rows i in [ILO, IHI] only (wedge pruning). Slot (T7+2)%7 completes.
#define STEP_RANGE(T7, ILO, IHI, DOSTORE) do {                                \
    const char* sb = (const char*)sbuf + offC + ty * (NQ * 256) + tx * 8;     \
    u64 w[8];                                                                 \
    _Pragma("unroll")                                                         \
    for (int d = 0; d < 8; ++d)                                               \
        w[d] = *(const u64*)(sb + d * 256);                                   \
    _Pragma("unroll")                                                         \
    for (int i = 0; i < 7; ++i) {                                             \
        if (i >= (ILO) && i <= (IHI)) {                                       \
            const int s = ((T7) + i + 2) % 7;                                 \
            _Pragma("unroll")                                                 \
            for (int j = 0; j < 7; ++j) {                                     \
                const u64 kv = kreg[i * 7 + j];                               \
                fma2(acc[s][0], kv, w[6 - j]);                                \
                fma2(acc[s][1], kv, w[7 - j]);                                \
            }                                                                 \
        }                                                                     \
    }                                                                         \
    {                                                                         \
        const int so = ((T7) + 2) % 7;                                        \
        if (DOSTORE) {                                                        \
            *(u64*)(out + outOff)      = acc[so][0];                          \
            *(u64*)(out + outOff + C_) = acc[so][1];                          \
            outOff += ROWSZ;                                                  \
        }                                                                     \
        acc[so][0] = 0ULL; acc[so][1] = 0ULL;                                 \
    }                                                                         \
    offC += STAGE_BYTES; if (offC >= RING_BYTES) offC -= RING_BYTES;          \
} while (0)

// 4-row macro: ONE wait + ONE barrier + ONE commit group per 4 rows.
// wait1: at entry pending = {G(t), G(t+4)} -> waits G(t) (rows t..t+3 landed).
// Issue G(t+8) AFTER the barrier: it overwrites stages of rows t-4..t-1,
// consumed last macro -- the barrier orders all warps' reads before the write.
#define MACRO4(Ta, La, Sa, Tb, Lb, Sb, Tc, Lc, Sc, Td, Ld, Sd) do {           \
    cp_wait1();                                                               \
    __syncthreads();                                                          \
    STAGE_GROUP();                                                            \
    STEP_RANGE(Ta, La, 6, Sa);                                                \
    STEP_RANGE(Tb, Lb, 6, Sb);                                                \
    STEP_RANGE(Tc, Lc, 6, Sc);                                                \
    STEP_RANGE(Td, Ld, 6, Sd);                                                \
} while (0)

__global__ void __launch_bounds__(NTHREADS, 3)
dwconv_pipe6(const float* __restrict__ x, const float* __restrict__ kern,
             float* __restrict__ out)
{
    __shared__ float sbuf[STAGES][SROW][64];   // 43,008 B (12-stage ring)

    const int tx  = threadIdx.x;           // channel pair 0..31
    const int ty  = threadIdx.y;           // q group 0..3
    const int tid = ty * PAIRS + tx;

    const int wt = blockIdx.x;              // 0..27
    const int ht = blockIdx.y;              // 0..3
    const int bz = blockIdx.z;              // 0..23
    const int b  = bz / 3;
    const int g  = bz % 3;

    const int qbase = wt * QT;
    const int p0    = ht * RH;              // p0 % 7 == 0
    const int cbase = g * 64;
    const int c0    = cbase + 2 * tx;

    // ---- 49 kernel taps for this channel pair -> registers (f32x2) ----
    u64 kreg[49];
    #pragma unroll
    for (int t = 0; t < 49; ++t)
        kreg[t] = pack2(kern[c0 * 49 + t], kern[(c0 + 1) * 49 + t]);

    // ---- balanced staging plan: float4 idx_k = tid + 128k, k = 0..6 ----
    // r_k = idx/224 (row in group), s_k = (idx%224)/16 (col), v = tid&15 (ch)
    int colOffA[7];
    #pragma unroll
    for (int k = 0; k < 7; ++k) {
        const int idx = tid + 128 * k;
        const int s   = (idx % 224) / 16;
        const int v   = tid & 15;
        int q = qbase - 3 + s;
        q += (q < 0) ? W_ : 0;
        q -= (q >= W_) ? W_ : 0;
        colOffA[k] = q * C_ + cbase + v * 4;
    }
    const int colOff0 = colOffA[0], colOff1 = colOffA[1], colOff2 = colOffA[2],
              colOff3 = colOffA[3], colOff4 = colOffA[4], colOff5 = colOffA[5],
              colOff6 = colOffA[6];
    const bool cls1 = tid < 96;   // k=1 row select (r=0 vs 1)
    const bool cls3 = tid < 64;   // k=3 row select (r=1 vs 2)
    const bool cls5 = tid < 32;   // k=5 row select (r=2 vs 3)
    const uint32_t sdst = smem_u32(&sbuf[0][0][0]) + (uint32_t)(tid * 16);

    // row cursor (circular over H, pointer-only)
    const float* const xBase = x + b * IMGSZ;
    const float* const xEnd  = xBase + IMGSZ;
    const float* rowPtr = xBase + (p0 - 3 < 0 ? p0 - 3 + H_ : p0 - 3) * ROWSZ;

    uint32_t offP = 0;                      // prefetch cursor (group-aligned)
    uint32_t offC = 0;                      // consume cursor (1 stage per row)

    // ---- prologue: G0 rows 0-3 -> stages 0-3, G1 rows 4-7 -> stages 4-7 ----
    STAGE_GROUP();
    STAGE_GROUP();

    // 7 rolling accumulators (static slots), f32x2 x NQ
    u64 acc[7][2];
    #pragma unroll
    for (int m = 0; m < 7; ++m) { acc[m][0] = 0ULL; acc[m][1] = 0ULL; }

    const int qOut = qbase + ty * NQ;
    int outOff = ((b * H_ + p0) * W_ + qOut) * C_ + c0;

    // ---- 14 macros, rows 0..55 (phases = row % 7; warm rows <6 pruned) ----
    MACRO4(0, 6, 0,  1, 5, 0,  2, 4, 0,  3, 3, 0);   // rows  0- 3 (no store)
    MACRO4(4, 2, 0,  5, 1, 0,  6, 0, 1,  0, 0, 1);   // rows  4- 7
    MACRO4(1, 0, 1,  2, 0, 1,  3, 0, 1,  4, 0, 1);   // rows  8-11
    MACRO4(5, 0, 1,  6, 0, 1,  0, 0, 1,  1, 0, 1);   // rows 12-15
    MACRO4(2, 0, 1,  3, 0, 1,  4, 0, 1,  5, 0, 1);   // rows 16-19
    MACRO4(6, 0, 1,  0, 0, 1,  1, 0, 1,  2, 0, 1);   // rows 20-23
    MACRO4(3, 0, 1,  4, 0, 1,  5, 0, 1,  6, 0, 1);   // rows 24-27
    MACRO4(0, 0, 1,  1, 0, 1,  2, 0, 1,  3, 0, 1);   // rows 28-31
    MACRO4(4, 0, 1,  5, 0, 1,  6, 0, 1,  0, 0, 1);   // rows 32-35
    MACRO4(1, 0, 1,  2, 0, 1,  3, 0, 1,  4, 0, 1);   // rows 36-39
    MACRO4(5, 0, 1,  6, 0, 1,  0, 0, 1,  1, 0, 1);   // rows 40-43
    MACRO4(2, 0, 1,  3, 0, 1,  4, 0, 1,  5, 0, 1);   // rows 44-47
    MACRO4(6, 0, 1,  0, 0, 1,  1, 0, 1,  2, 0, 1);   // rows 48-51
    MACRO4(3, 0, 1,  4, 0, 1,  5, 0, 1,  6, 0, 1);   // rows 52-55

    // ---- tail: rows 56..61, wedge-pruned (i <= 61-t), all groups landed ----
    cp_wait0();
    __syncthreads();
    STEP_RANGE(0, 0, 5, 1);
    STEP_RANGE(1, 0, 4, 1);
    STEP_RANGE(2, 0, 3, 1);
    STEP_RANGE(3, 0, 2, 1);
    STEP_RANGE(4, 0, 1, 1);
    STEP_RANGE(5, 0, 0, 1);
}

extern "C" void kernel_launch(void* const* d_in, const int* in_sizes, int n_in,
                              void* d_out, int out_size) {
    const float* x    = (const float*)d_in[0];   // (8,224,224,192) fp32
    const float* kern = (const float*)d_in[1];   // (192,7,7) fp32
    float* out        = (float*)d_out;           // (8,224,224,192) fp32

    dim3 grid(W_ / QT, H_ / RH, B_ * 3);  // 28 x 4 x 24 = 2688 blocks
    dim3 block(PAIRS, QTH, 1);            // 128 threads
    dwconv_pipe6<<<grid, block>>>(x, kern, out);
}

// round 12
// speedup vs baseline: 1.2195x; 1.1586x over previous
#include <cuda_runtime.h>
#include <cstdint>

#define B_  8
#define H_  224
#define W_  224
#define C_  192
#define QT  8        // q positions per block
#define NQ  2        // q per thread
#define PAIRS 32     // channel pairs (threadIdx.x)
#define QTH  4       // q-thread groups (threadIdx.y)
#define NTHREADS 128
#define RH  56       // output rows per block
#define SROW 14      // staged columns per row (QT + 6)
#define STAGES 8
#define STAGE_BYTES (SROW * 64 * 4)          // 3584 B per stage
#define RING_BYTES  (STAGES * STAGE_BYTES)   // 28672 B
#define ROWSZ (W_ * C_)
#define IMGSZ (H_ * W_ * C_)

typedef unsigned long long u64;

__device__ __forceinline__ void fma2(u64 &d, u64 a, u64 b) {
    asm("fma.rn.f32x2 %0, %1, %2, %0;" : "+l"(d) : "l"(a), "l"(b));
}
__device__ __forceinline__ void cpasync16(uint32_t dst, const float* src) {
    asm volatile("cp.async.cg.shared.global [%0], [%1], 16;" :: "r"(dst), "l"(src));
}
__device__ __forceinline__ void cp_commit() {
    asm volatile("cp.async.commit_group;" ::: "memory");
}
__device__ __forceinline__ void cp_wait2() {
    asm volatile("cp.async.wait_group 2;" ::: "memory");
}
__device__ __forceinline__ void cp_wait0() {
    asm volatile("cp.async.wait_group 0;" ::: "memory");
}
__device__ __forceinline__ uint32_t smem_u32(const void* p) {
    uint32_t a;
    asm("{ .reg .u64 t; cvta.to.shared.u64 t, %1; cvt.u32.u64 %0, t; }" : "=r"(a) : "l"(p));
    return a;
}

// Compute half-step at row phase T7 (t % 7), stage byte offset SOFF.
// Kernel rows i in [ILO, IHI] only (wedge pruning). Slot (T7+2)%7 completes.
#define STEP_RANGE(T7, ILO, IHI, SOFF, DOSTORE) do {                          \
    const char* sb = (const char*)sbuf + (SOFF) + ty * (NQ * 256) + tx * 8;   \
    u64 w[8];                                                                 \
    _Pragma("unroll")                                                         \
    for (int d = 0; d < 8; ++d)                                               \
        w[d] = *(const u64*)(sb + d * 256);                                   \
    _Pragma("unroll")                                                         \
    for (int i = 0; i < 7; ++i) {                                             \
        if (i >= (ILO) && i <= (IHI)) {                                       \
            const int s = ((T7) + i + 2) % 7;                                 \
            _Pragma("unroll")                                                 \
            for (int j = 0; j < 7; ++j) {                                     \
                const u64 kv = kreg[i * 7 + j];                               \
                fma2(acc[s][0], kv, w[6 - j]);                                \
                fma2(acc[s][1], kv, w[7 - j]);                                \
            }                                                                 \
        }                                                                     \
    }                                                                         \
    {                                                                         \
        const int so = ((T7) + 2) % 7;                                        \
        if (DOSTORE) {                                                        \
            *(u64*)(out + outOff)      = acc[so][0];                          \
            *(u64*)(out + outOff + C_) = acc[so][1];                          \
            outOff += ROWSZ;                                                  \
        }                                                                     \
        acc[so][0] = 0ULL; acc[so][1] = 0ULL;                                 \
    }                                                                         \
} while (0)

// Macro step: one wait + one barrier + one commit group for TWO rows.
#define MACRO2R(T7a, LOa, T7b, LOb, DOSTORE) do {                             \
    cp_wait2();                                                               \
    __syncthreads();                                                          \
    {                                                                         \
        const uint32_t dA = sdst + offP;                                      \
        cpasync16(dA, rowPtr + colOff0);                                      \
        if (has1) cpasync16(dA + 2048, rowPtr + colOff1);                     \
        rowPtr += ROWSZ; if (rowPtr >= xEnd) rowPtr -= IMGSZ;                 \
        uint32_t p2 = offP + STAGE_BYTES;                                     \
        if (p2 >= RING_BYTES) p2 -= RING_BYTES;                               \
        const uint32_t dB = sdst + p2;                                        \
        cpasync16(dB, rowPtr + colOff0);                                      \
        if (has1) cpasync16(dB + 2048, rowPtr + colOff1);                     \
        rowPtr += ROWSZ; if (rowPtr >= xEnd) rowPtr -= IMGSZ;                 \
        cp_commit();                                                          \
        offP += 2 * STAGE_BYTES; if (offP >= RING_BYTES) offP -= RING_BYTES;  \
    }                                                                         \
    STEP_RANGE(T7a, LOa, 6, offCa, DOSTORE);                                  \
    offCa += 2 * STAGE_BYTES; if (offCa >= RING_BYTES) offCa -= RING_BYTES;   \
    STEP_RANGE(T7b, LOb, 6, offCb, DOSTORE);                                  \
    offCb += 2 * STAGE_BYTES; if (offCb >= RING_BYTES) offCb -= RING_BYTES;   \
} while (0)

// 7 macro steps = 14 rows (acc phase period). Starts at t%7 == 6.
#define GROUP7M()                                                             \
    MACRO2R(6, 0, 0, 0, 1); MACRO2R(1, 0, 2, 0, 1); MACRO2R(3, 0, 4, 0, 1);   \
    MACRO2R(5, 0, 6, 0, 1); MACRO2R(0, 0, 1, 0, 1); MACRO2R(2, 0, 3, 0, 1);   \
    MACRO2R(4, 0, 5, 0, 1)

#define TAILSTEP(T7, IHI, CUR) do {                                           \
    STEP_RANGE(T7, 0, IHI, CUR, 1);                                           \
    CUR += 2 * STAGE_BYTES; if (CUR >= RING_BYTES) CUR -= RING_BYTES;         \
} while (0)

__global__ void __launch_bounds__(NTHREADS, 3)
dwconv_pipe7(const float* __restrict__ x, const float* __restrict__ kern,
             float* __restrict__ out)
{
    __shared__ float sbuf[STAGES][SROW][64];   // 28,672 B ring (also weight temp)

    const int tx  = threadIdx.x;           // channel pair 0..31
    const int ty  = threadIdx.y;           // q group 0..3
    const int tid = ty * PAIRS + tx;

    const int wt = blockIdx.x;              // 0..27
    const int ht = blockIdx.y;              // 0..3
    const int bz = blockIdx.z;              // 0..23
    const int b  = bz / 3;
    const int g  = bz % 3;

    const int qbase = wt * QT;
    const int p0    = ht * RH;              // p0 % 7 == 0
    const int cbase = g * 64;
    const int c0    = cbase + 2 * tx;

    // ---- fast weight load: coalesced LDG -> smem transpose -> LDS.64 ----
    // Slab kern[cbase*49 .. +3136) loaded as 784 float4 (fully coalesced),
    // scattered into smw[t*64 + c]; then each thread reads its 49 channel-pair
    // taps as conflict-free LDS.64. Replaces 98 divergent 392B-stride LDG.32.
    u64 kreg[49];
    {
        float* smw = &sbuf[0][0][0];            // 12,544 B of ring reused
        const float4* kslab = (const float4*)(kern + cbase * 49);  // 16B-aligned
        #pragma unroll
        for (int i = tid; i < 784; i += NTHREADS) {
            const float4 v = kslab[i];
            const int base = i * 4;             // = c*49 + t
            #pragma unroll
            for (int e = 0; e < 4; ++e) {
                const int idx = base + e;
                const int c = idx / 49;
                const int t = idx - c * 49;
                smw[t * 64 + c] = (&v.x)[e];
            }
        }
        __syncthreads();
        #pragma unroll
        for (int t = 0; t < 49; ++t)
            kreg[t] = *(const u64*)(smw + t * 64 + 2 * tx);
        __syncthreads();                         // ring staging reuses sbuf below
    }

    // ---- cp.async staging plan: 224 float4 per stage, threads 0..95 take 2 ----
    const int s0 = tid >> 4, v0 = tid & 15;             // cols 0..7
    const bool has1 = tid < 96;
    const int s1 = (tid + 128) >> 4;                    // cols 8..13
    int qg0 = qbase - 3 + s0; qg0 += (qg0 < 0) ? W_ : 0; qg0 -= (qg0 >= W_) ? W_ : 0;
    int qg1 = qbase - 3 + s1; qg1 += (qg1 < 0) ? W_ : 0; qg1 -= (qg1 >= W_) ? W_ : 0;
    const int colOff0 = qg0 * C_ + cbase + v0 * 4;
    const int colOff1 = qg1 * C_ + cbase + v0 * 4;
    const uint32_t sdst = smem_u32(&sbuf[0][0][0]) + (uint32_t)(s0 * 256 + v0 * 16);

    // row cursor (circular over H, pointer-only)
    const float* const xBase = x + b * IMGSZ;
    const float* const xEnd  = xBase + IMGSZ;
    const float* rowPtr = xBase + (p0 - 3 < 0 ? p0 - 3 + H_ : p0 - 3) * ROWSZ;

    // ---- prologue: stage rows 0..5 into stages 0..5 (3 groups of 2 rows) ----
    #pragma unroll
    for (int pr = 0; pr < 3; ++pr) {
        uint32_t dA = sdst + (2 * pr) * STAGE_BYTES;
        cpasync16(dA, rowPtr + colOff0);
        if (has1) cpasync16(dA + 2048, rowPtr + colOff1);
        rowPtr += ROWSZ; if (rowPtr >= xEnd) rowPtr -= IMGSZ;
        uint32_t dB = sdst + (2 * pr + 1) * STAGE_BYTES;
        cpasync16(dB, rowPtr + colOff0);
        if (has1) cpasync16(dB + 2048, rowPtr + colOff1);
        rowPtr += ROWSZ; if (rowPtr >= xEnd) rowPtr -= IMGSZ;
        cp_commit();
    }

    uint32_t offCa = 0;
    uint32_t offCb = STAGE_BYTES;
    uint32_t offP  = 6 * STAGE_BYTES;

    // 7 rolling accumulators (static slots), f32x2 x NQ
    u64 acc[7][2];
    #pragma unroll
    for (int m = 0; m < 7; ++m) { acc[m][0] = 0ULL; acc[m][1] = 0ULL; }

    const int qOut = qbase + ty * NQ;
    int outOff = ((b * H_ + p0) * W_ + qOut) * C_ + c0;

    // ---- warm-up: rows t = 0..5, wedge-pruned (i >= 6-t), no stores ----
    MACRO2R(0, 6, 1, 5, 0);
    MACRO2R(2, 4, 3, 3, 0);
    MACRO2R(4, 2, 5, 1, 0);

    // ---- main: rows t = 6..47, three 7-macro groups (I$-resident) ----
    #pragma unroll 1
    for (int o = 0; o < 3; ++o) {
        GROUP7M();
    }
    // ---- main remainder: rows t = 48..55 ----
    MACRO2R(6, 0, 0, 0, 1);
    MACRO2R(1, 0, 2, 0, 1);
    MACRO2R(3, 0, 4, 0, 1);
    MACRO2R(5, 0, 6, 0, 1);

    // ---- tail: rows t = 56..61, wedge-pruned (i <= 61-t), all data staged ----
    cp_wait0();
    __syncthreads();
    TAILSTEP(0, 5, offCa);
    TAILSTEP(1, 4, offCb);
    TAILSTEP(2, 3, offCa);
    TAILSTEP(3, 2, offCb);
    TAILSTEP(4, 1, offCa);
    TAILSTEP(5, 0, offCb);
}

extern "C" void kernel_launch(void* const* d_in, const int* in_sizes, int n_in,
                              void* d_out, int out_size) {
    const float* x    = (const float*)d_in[0];   // (8,224,224,192) fp32
    const float* kern = (const float*)d_in[1];   // (192,7,7) fp32
    float* out        = (float*)d_out;           // (8,224,224,192) fp32

    dim3 grid(W_ / QT, H_ / RH, B_ * 3);  // 28 x 4 x 24 = 2688 blocks
    dim3 block(PAIRS, QTH, 1);            // 128 threads
    dwconv_pipe7<<<grid, block>>>(x, kern, out);
}

// round 13
// speedup vs baseline: 1.2414x; 1.0180x over previous
#include <cuda_runtime.h>
#include <cstdint>

#define B_  8
#define H_  224
#define W_  224
#define C_  192
#define QT  8        // q positions per block
#define NQ  2        // q per thread
#define PAIRS 32     // channel pairs (threadIdx.x)
#define QTH  4       // q-thread groups (threadIdx.y)
#define NTHREADS 128
#define RH  56       // output rows per block
#define SROW 14      // staged columns per row (QT + 6)
#define STAGES 8
#define STAGE_BYTES (SROW * 64 * 4)          // 3584 B per stage
#define RING_BYTES  (STAGES * STAGE_BYTES)   // 28672 B
#define ROWSZ (W_ * C_)
#define IMGSZ (H_ * W_ * C_)

typedef unsigned long long u64;

__device__ __forceinline__ void fma2(u64 &d, u64 a, u64 b) {
    asm("fma.rn.f32x2 %0, %1, %2, %0;" : "+l"(d) : "l"(a), "l"(b));
}
__device__ __forceinline__ void cpasync16(uint32_t dst, const float* src) {
    asm volatile("cp.async.cg.shared.global [%0], [%1], 16;" :: "r"(dst), "l"(src));
}
__device__ __forceinline__ void cp_commit() {
    asm volatile("cp.async.commit_group;" ::: "memory");
}
__device__ __forceinline__ void cp_wait2() {
    asm volatile("cp.async.wait_group 2;" ::: "memory");
}
__device__ __forceinline__ void cp_wait0() {
    asm volatile("cp.async.wait_group 0;" ::: "memory");
}
__device__ __forceinline__ uint32_t smem_u32(const void* p) {
    uint32_t a;
    asm("{ .reg .u64 t; cvta.to.shared.u64 t, %1; cvt.u32.u64 %0, t; }" : "=r"(a) : "l"(p));
    return a;
}

// Compute half-step at row phase T7 (t % 7), stage byte offset SOFF.
// Kernel rows i in [ILO, IHI] only (wedge pruning). Slot (T7+2)%7 completes.
#define STEP_RANGE(T7, ILO, IHI, SOFF, DOSTORE) do {                          \
    const char* sb = (const char*)sbuf + (SOFF) + ty * (NQ * 256) + tx * 8;   \
    u64 w[8];                                                                 \
    _Pragma("unroll")                                                         \
    for (int d = 0; d < 8; ++d)                                               \
        w[d] = *(const u64*)(sb + d * 256);                                   \
    _Pragma("unroll")                                                         \
    for (int i = 0; i < 7; ++i) {                                             \
        if (i >= (ILO) && i <= (IHI)) {                                       \
            const int s = ((T7) + i + 2) % 7;                                 \
            _Pragma("unroll")                                                 \
            for (int j = 0; j < 7; ++j) {                                     \
                const u64 kv = kreg[i * 7 + j];                               \
                fma2(acc[s][0], kv, w[6 - j]);                                \
                fma2(acc[s][1], kv, w[7 - j]);                                \
            }                                                                 \
        }                                                                     \
    }                                                                         \
    {                                                                         \
        const int so = ((T7) + 2) % 7;                                        \
        if (DOSTORE) {                                                        \
            *(u64*)(out + outOff)      = acc[so][0];                          \
            *(u64*)(out + outOff + C_) = acc[so][1];                          \
            outOff += ROWSZ;                                                  \
        }                                                                     \
        acc[so][0] = 0ULL; acc[so][1] = 0ULL;                                 \
    }                                                                         \
} while (0)

// Macro step: one wait + one barrier + one commit group for TWO rows.
#define MACRO2R(T7a, LOa, T7b, LOb, DOSTORE) do {                             \
    cp_wait2();                                                               \
    __syncthreads();                                                          \
    {                                                                         \
        const uint32_t dA = sdst + offP;                                      \
        cpasync16(dA, rowPtr + colOff0);                                      \
        if (has1) cpasync16(dA + 2048, rowPtr + colOff1);                     \
        rowPtr += ROWSZ; if (rowPtr >= xEnd) rowPtr -= IMGSZ;                 \
        uint32_t p2 = offP + STAGE_BYTES;                                     \
        if (p2 >= RING_BYTES) p2 -= RING_BYTES;                               \
        const uint32_t dB = sdst + p2;                                        \
        cpasync16(dB, rowPtr + colOff0);                                      \
        if (has1) cpasync16(dB + 2048, rowPtr + colOff1);                     \
        rowPtr += ROWSZ; if (rowPtr >= xEnd) rowPtr -= IMGSZ;                 \
        cp_commit();                                                          \
        offP += 2 * STAGE_BYTES; if (offP >= RING_BYTES) offP -= RING_BYTES;  \
    }                                                                         \
    STEP_RANGE(T7a, LOa, 6, offCa, DOSTORE);                                  \
    offCa += 2 * STAGE_BYTES; if (offCa >= RING_BYTES) offCa -= RING_BYTES;   \
    STEP_RANGE(T7b, LOb, 6, offCb, DOSTORE);                                  \
    offCb += 2 * STAGE_BYTES; if (offCb >= RING_BYTES) offCb -= RING_BYTES;   \
} while (0)

// 7 macro steps = 14 rows (acc phase period). Starts at t%7 == 6.
#define GROUP7M()                                                             \
    MACRO2R(6, 0, 0, 0, 1); MACRO2R(1, 0, 2, 0, 1); MACRO2R(3, 0, 4, 0, 1);   \
    MACRO2R(5, 0, 6, 0, 1); MACRO2R(0, 0, 1, 0, 1); MACRO2R(2, 0, 3, 0, 1);   \
    MACRO2R(4, 0, 5, 0, 1)

#define TAILSTEP(T7, IHI, CUR) do {                                           \
    STEP_RANGE(T7, 0, IHI, CUR, 1);                                           \
    CUR += 2 * STAGE_BYTES; if (CUR >= RING_BYTES) CUR -= RING_BYTES;         \
} while (0)

__global__ void __launch_bounds__(NTHREADS, 3)
dwconv_pipe8(const float* __restrict__ x, const float* __restrict__ kern,
             float* __restrict__ out)
{
    __shared__ float sbuf[STAGES][SROW][64];   // 28,672 B input ring
    __shared__ float swt[49][64];              // 12,544 B weight transpose buf

    const int tx  = threadIdx.x;           // channel pair 0..31
    const int ty  = threadIdx.y;           // q group 0..3
    const int tid = ty * PAIRS + tx;

    const int wt = blockIdx.x;              // 0..27
    const int ht = blockIdx.y;              // 0..3
    const int bz = blockIdx.z;              // 0..23
    const int b  = bz / 3;
    const int g  = bz % 3;

    const int qbase = wt * QT;
    const int p0    = ht * RH;              // p0 % 7 == 0
    const int cbase = g * 64;
    const int c0    = cbase + 2 * tx;

    // ---- cp.async staging plan: 224 float4 per stage, threads 0..95 take 2 ----
    const int s0 = tid >> 4, v0 = tid & 15;             // cols 0..7
    const bool has1 = tid < 96;
    const int s1 = (tid + 128) >> 4;                    // cols 8..13
    int qg0 = qbase - 3 + s0; qg0 += (qg0 < 0) ? W_ : 0; qg0 -= (qg0 >= W_) ? W_ : 0;
    int qg1 = qbase - 3 + s1; qg1 += (qg1 < 0) ? W_ : 0; qg1 -= (qg1 >= W_) ? W_ : 0;
    const int colOff0 = qg0 * C_ + cbase + v0 * 4;
    const int colOff1 = qg1 * C_ + cbase + v0 * 4;
    const uint32_t sdst = smem_u32(&sbuf[0][0][0]) + (uint32_t)(s0 * 256 + v0 * 16);

    // row cursor (circular over H, pointer-only)
    const float* const xBase = x + b * IMGSZ;
    const float* const xEnd  = xBase + IMGSZ;
    const float* rowPtr = xBase + (p0 - 3 < 0 ? p0 - 3 + H_ : p0 - 3) * ROWSZ;

    // ---- FIRST: launch prologue cp.asyncs (rows 0..5 -> stages 0..5) so the
    // DRAM latency of the first rows overlaps the weight load below ----
    #pragma unroll
    for (int pr = 0; pr < 3; ++pr) {
        uint32_t dA = sdst + (2 * pr) * STAGE_BYTES;
        cpasync16(dA, rowPtr + colOff0);
        if (has1) cpasync16(dA + 2048, rowPtr + colOff1);
        rowPtr += ROWSZ; if (rowPtr >= xEnd) rowPtr -= IMGSZ;
        uint32_t dB = sdst + (2 * pr + 1) * STAGE_BYTES;
        cpasync16(dB, rowPtr + colOff0);
        if (has1) cpasync16(dB + 2048, rowPtr + colOff1);
        rowPtr += ROWSZ; if (rowPtr >= xEnd) rowPtr -= IMGSZ;
        cp_commit();
    }

    // ---- weight load (overlapped with prologue flight): coalesced LDG of the
    // 64-ch slab as 784 float4 -> transpose into swt[t][c] -> LDS.64 taps ----
    u64 kreg[49];
    {
        const float4* kslab = (const float4*)(kern + cbase * 49);  // 16B-aligned
        #pragma unroll
        for (int i = tid; i < 784; i += NTHREADS) {
            const float4 v = kslab[i];
            const int base = i * 4;             // = c*49 + t
            #pragma unroll
            for (int e = 0; e < 4; ++e) {
                const int idx = base + e;
                const int c = idx / 49;
                const int t = idx - c * 49;
                swt[t][c] = (&v.x)[e];
            }
        }
        __syncthreads();
        #pragma unroll
        for (int t = 0; t < 49; ++t)
            kreg[t] = *(const u64*)(&swt[t][2 * tx]);
    }

    uint32_t offCa = 0;
    uint32_t offCb = STAGE_BYTES;
    uint32_t offP  = 6 * STAGE_BYTES;

    // 7 rolling accumulators (static slots), f32x2 x NQ
    u64 acc[7][2];
    #pragma unroll
    for (int m = 0; m < 7; ++m) { acc[m][0] = 0ULL; acc[m][1] = 0ULL; }

    const int qOut = qbase + ty * NQ;
    int outOff = ((b * H_ + p0) * W_ + qOut) * C_ + c0;

    // ---- warm-up: rows t = 0..5, wedge-pruned (i >= 6-t), no stores ----
    MACRO2R(0, 6, 1, 5, 0);
    MACRO2R(2, 4, 3, 3, 0);
    MACRO2R(4, 2, 5, 1, 0);

    // ---- main: rows t = 6..47, three 7-macro groups (I$-resident) ----
    #pragma unroll 1
    for (int o = 0; o < 3; ++o) {
        GROUP7M();
    }
    // ---- main remainder: rows t = 48..55 ----
    MACRO2R(6, 0, 0, 0, 1);
    MACRO2R(1, 0, 2, 0, 1);
    MACRO2R(3, 0, 4, 0, 1);
    MACRO2R(5, 0, 6, 0, 1);

    // ---- tail: rows t = 56..61, wedge-pruned (i <= 61-t), all data staged ----
    cp_wait0();
    __syncthreads();
    TAILSTEP(0, 5, offCa);
    TAILSTEP(1, 4, offCb);
    TAILSTEP(2, 3, offCa);
    TAILSTEP(3, 2, offCb);
    TAILSTEP(4, 1, offCa);
    TAILSTEP(5, 0, offCb);
}

extern "C" void kernel_launch(void* const* d_in, const int* in_sizes, int n_in,
                              void* d_out, int out_size) {
    const float* x    = (const float*)d_in[0];   // (8,224,224,192) fp32
    const float* kern = (const float*)d_in[1];   // (192,7,7) fp32
    float* out        = (float*)d_out;           // (8,224,224,192) fp32

    dim3 grid(W_ / QT, H_ / RH, B_ * 3);  // 28 x 4 x 24 = 2688 blocks
    dim3 block(PAIRS, QTH, 1);            // 128 threads
    dwconv_pipe8<<<grid, block>>>(x, kern, out);
}